// round 5
// baseline (speedup 1.0000x reference)
#include <cuda_runtime.h>
#include <cuda_bf16.h>
#include <cstdint>

#define NB      16
#define CIN     256
#define COUT    256
#define HWSZ    1024
#define PT      128
#define NSTAGE  128          // 2 input channels per stage
#define NT      512          // 16 warps, 4(M) x 4(N)

// K layout per stage (56 bf16 cols): [vhi ch0(9) ch1(9) | vlo ch0 ch1 | vhi ch0 ch1 | pad2]
// B mirrors:                         [whi            | whi          | wlo        | 0   ]
#define A_STRIDE 112                 // 56 cols exactly; 28-word stride -> ldmatrix conflict-free
#define A_SZ     (128 * A_STRIDE)    // 14336
#define B_STRIDE 528                 // 256 cols + 8 pad
#define B_SZ     (56 * B_STRIDE)     // 29568
#define X_SZ     8192                // 2 channels x 1024 float
#define A_OFF    0
#define B_OFF    (2 * A_SZ)          // 28672
#define X_OFF    (B_OFF + 2 * B_SZ)  // 87808
#define SMEM_DYN (X_OFF + 3 * X_SZ)  // 112384

// packed weights: [stage][56 k][256 o] bf16, rows 512B (pads pre-zeroed)
__device__ __align__(16) unsigned char g_wp[(size_t)NSTAGE * 56 * 512];

// ---------------- helpers ----------------
__device__ __forceinline__ uint32_t smem_u32(const void* p) {
    uint32_t a;
    asm("{ .reg .u64 t; cvta.to.shared.u64 t, %1; cvt.u32.u64 %0, t; }" : "=r"(a) : "l"(p));
    return a;
}
__device__ __forceinline__ void cp16(uint32_t d, const void* g) {
    asm volatile("cp.async.cg.shared.global [%0], [%1], 16;" :: "r"(d), "l"(g));
}
#define CP_COMMIT() asm volatile("cp.async.commit_group;" ::: "memory")
#define CP_WAIT0()  asm volatile("cp.async.wait_group 0;" ::: "memory")

__device__ __forceinline__ void ldm_x4(uint32_t r[4], uint32_t a) {
    asm volatile("ldmatrix.sync.aligned.m8n8.x4.shared.b16 {%0,%1,%2,%3}, [%4];"
                 : "=r"(r[0]), "=r"(r[1]), "=r"(r[2]), "=r"(r[3]) : "r"(a));
}
__device__ __forceinline__ void ldm_x4_t(uint32_t r[4], uint32_t a) {
    asm volatile("ldmatrix.sync.aligned.m8n8.x4.trans.shared.b16 {%0,%1,%2,%3}, [%4];"
                 : "=r"(r[0]), "=r"(r[1]), "=r"(r[2]), "=r"(r[3]) : "r"(a));
}
__device__ __forceinline__ void mma16816(float d[4], const uint32_t a[4], const uint32_t b[2]) {
    asm volatile("mma.sync.aligned.m16n8k16.row.col.f32.bf16.bf16.f32 "
                 "{%0,%1,%2,%3},{%4,%5,%6,%7},{%8,%9},{%0,%1,%2,%3};"
                 : "+f"(d[0]), "+f"(d[1]), "+f"(d[2]), "+f"(d[3])
                 : "r"(a[0]), "r"(a[1]), "r"(a[2]), "r"(a[3]), "r"(b[0]), "r"(b[1]));
}
__device__ __forceinline__ void mma1688(float d[4], const uint32_t a[2], uint32_t b) {
    asm volatile("mma.sync.aligned.m16n8k8.row.col.f32.bf16.bf16.f32 "
                 "{%0,%1,%2,%3},{%4,%5},{%6},{%0,%1,%2,%3};"
                 : "+f"(d[0]), "+f"(d[1]), "+f"(d[2]), "+f"(d[3])
                 : "r"(a[0]), "r"(a[1]), "r"(b));
}

// ---------------- weight prep: split hi/lo, k-major, coalesced 8B writes ----------------
__global__ void prep_weights(const float* __restrict__ weight) {
    const int j = blockIdx.x * blockDim.x + threadIdx.x;   // 128*56*64
    if (j >= NSTAGE * 56 * 64) return;
    const int o4 = j & 63;
    const int kcol = (j >> 6) % 56;
    const int s = j / (56 * 64);
    __nv_bfloat16 v[4];
    if (kcol >= 54) {
        v[0] = v[1] = v[2] = v[3] = __float2bfloat16(0.f);
    } else {
        const int t = kcol / 18, r = kcol % 18, ch = r / 9, k = r % 9;
        #pragma unroll
        for (int i = 0; i < 4; ++i) {
            const float w = weight[(size_t)(4 * o4 + i) * 2304 + (2 * s + ch) * 9 + k];
            const __nv_bfloat16 hi = __float2bfloat16(w);
            v[i] = (t == 2) ? __float2bfloat16(w - __bfloat162float(hi)) : hi;
        }
    }
    *(uint2*)(g_wp + ((size_t)s * 56 + kcol) * 512 + o4 * 8) = *(const uint2*)v;
}

// ---------------- main kernel ----------------
__global__ __launch_bounds__(NT)
void dcn_mma_kernel(const float* __restrict__ x,
                    const float* __restrict__ offset,
                    float* __restrict__ out)
{
    extern __shared__ char sm[];
    const uint32_t sb = smem_u32(sm);

    const int tid  = threadIdx.x;
    const int wid  = tid >> 5, lane = tid & 31;
    const int n    = blockIdx.y;
    const int p0   = blockIdx.x * PT;
    const int warpM = wid & 3;     // 4 M-tiles of 32
    const int warpN = wid >> 2;    // 4 N-tiles of 64

    // zero A pad cols (bytes 108..111) of both buffers
    if (tid < 256)
        *(uint32_t*)(sm + A_OFF + (tid >> 7) * A_SZ + (tid & 127) * A_STRIDE + 108) = 0;

    // ---- sampling tables -> registers (3 entries/thread) ----
    uint32_t tlo[3], thi[3];
    float4 twt[3];
    #pragma unroll
    for (int e = 0; e < 3; ++e) {
        const int j = tid + e * NT;
        if (j < 9 * PT) {
            const int k = j >> 7, p = j & 127;
            const int gp = p0 + p;
            const float2 d2 = *reinterpret_cast<const float2*>(
                offset + ((size_t)n * HWSZ + gp) * 18 + 2 * k);
            const float py = (float)(gp >> 5) + (float)(k / 3 - 1) + d2.x;
            const float px = (float)(gp & 31) + (float)(k % 3 - 1) + d2.y;
            const float y0 = floorf(py), x0 = floorf(px);
            const float ly = py - y0, lx = px - x0;
            const float hy = 1.f - ly, hx = 1.f - lx;
            const float vy0 = (y0 >= 0.f && y0 <= 31.f) ? 1.f : 0.f;
            const float vy1 = (y0 >= -1.f && y0 <= 30.f) ? 1.f : 0.f;
            const float vx0 = (x0 >= 0.f && x0 <= 31.f) ? 1.f : 0.f;
            const float vx1 = (x0 >= -1.f && x0 <= 30.f) ? 1.f : 0.f;
            const uint32_t iy0 = (uint32_t)(int)fminf(fmaxf(y0, 0.f), 31.f);
            const uint32_t iy1 = (uint32_t)(int)fminf(fmaxf(y0 + 1.f, 0.f), 31.f);
            const uint32_t ix0 = (uint32_t)(int)fminf(fmaxf(x0, 0.f), 31.f);
            const uint32_t ix1 = (uint32_t)(int)fminf(fmaxf(x0 + 1.f, 0.f), 31.f);
            tlo[e] = (iy0 * 32 + ix0) | ((iy0 * 32 + ix1) << 16);
            thi[e] = (iy1 * 32 + ix0) | ((iy1 * 32 + ix1) << 16);
            twt[e] = make_float4(hy * hx * vy0 * vx0, hy * lx * vy0 * vx1,
                                 ly * hx * vy1 * vx0, ly * lx * vy1 * vx1);
        } else {
            tlo[e] = thi[e] = 0;
            twt[e] = make_float4(0.f, 0.f, 0.f, 0.f);
        }
    }

    const float* xn = x + (size_t)n * CIN * HWSZ;

    // ---- async staging ----
    auto issue_b = [&](int st) {   // B(st) <- g_wp[st], 1792 x 16B
        const char* gsrc = (const char*)g_wp + (size_t)st * (56 * 512);
        const uint32_t bdst = sb + B_OFF + (st & 1) * B_SZ;
        #pragma unroll
        for (int q = 0; q < 4; ++q) {
            const int idx = tid + q * NT;
            if (q < 3 || idx < 1792) {
                const int row = idx >> 5, ch = idx & 31;
                cp16(bdst + row * B_STRIDE + ch * 16, gsrc + row * 512 + ch * 16);
            }
        }
    };
    auto issue_x = [&](int st) {   // x(st) = channels 2st,2st+1 = contiguous 8KB
        cp16(sb + X_OFF + (st % 3) * X_SZ + tid * 16,
             (const char*)(xn + (size_t)(2 * st) * HWSZ) + tid * 16);
    };

    // ---- build deformed, bf16-split A tile ----
    auto build_a = [&](int st) {
        const float* xp0 = (const float*)(sm + X_OFF + (st % 3) * X_SZ);
        const float* xp1 = xp0 + 1024;
        char* abuf = sm + A_OFF + (st & 1) * A_SZ;
        #pragma unroll
        for (int e = 0; e < 3; ++e) {
            const int j = tid + e * NT;
            if (e == 2 && j >= 9 * PT) break;
            const int k = j >> 7, p = j & 127;
            const int i00 = tlo[e] & 0xFFFF, i01 = tlo[e] >> 16;
            const int i10 = thi[e] & 0xFFFF, i11 = thi[e] >> 16;
            const float4 w = twt[e];
            const float v0 = w.x * xp0[i00] + w.y * xp0[i01] + w.z * xp0[i10] + w.w * xp0[i11];
            const float v1 = w.x * xp1[i00] + w.y * xp1[i01] + w.z * xp1[i10] + w.w * xp1[i11];
            const __nv_bfloat16 h0 = __float2bfloat16(v0);
            const __nv_bfloat16 l0 = __float2bfloat16(v0 - __bfloat162float(h0));
            const __nv_bfloat16 h1 = __float2bfloat16(v1);
            const __nv_bfloat16 l1 = __float2bfloat16(v1 - __bfloat162float(h1));
            char* row = abuf + p * A_STRIDE;
            *(__nv_bfloat16*)(row + 2 * k)      = h0;   // vhi ch0
            *(__nv_bfloat16*)(row + 18 + 2 * k) = h1;   // vhi ch1
            *(__nv_bfloat16*)(row + 36 + 2 * k) = l0;   // vlo ch0
            *(__nv_bfloat16*)(row + 54 + 2 * k) = l1;   // vlo ch1
            *(__nv_bfloat16*)(row + 72 + 2 * k) = h0;   // vhi ch0 (x wlo)
            *(__nv_bfloat16*)(row + 90 + 2 * k) = h1;   // vhi ch1 (x wlo)
        }
    };

    // ---- accumulators ----
    float acc[2][8][4];
    #pragma unroll
    for (int i = 0; i < 2; ++i)
        #pragma unroll
        for (int j = 0; j < 8; ++j)
            #pragma unroll
            for (int q = 0; q < 4; ++q) acc[i][j][q] = 0.f;

    // ldmatrix address components (constant across stages)
    const uint32_t aRowOff  = (uint32_t)(warpM * 32 + (lane & 15)) * A_STRIDE
                            + (uint32_t)(lane >> 4) * 16;
    const uint32_t aTailOff = (uint32_t)(warpM * 32 + lane) * A_STRIDE + 96;
    const uint32_t bRowOff  = (uint32_t)(lane & 15) * B_STRIDE
                            + (uint32_t)(warpN * 128) + (uint32_t)(lane >> 4) * 16;
    const uint32_t bTailOff = (uint32_t)(48 + (lane & 7)) * B_STRIDE
                            + (uint32_t)(warpN * 128) + (uint32_t)((lane >> 3) & 3) * 16;

    auto mma_stage = [&](int st) {
        const uint32_t ab = sb + A_OFF + (st & 1) * A_SZ;
        const uint32_t bb = sb + B_OFF + (st & 1) * B_SZ;
        #pragma unroll
        for (int kc = 0; kc < 3; ++kc) {
            uint32_t a0[4], a1[4];
            ldm_x4(a0, ab + aRowOff + kc * 32);
            ldm_x4(a1, ab + aRowOff + 16 * A_STRIDE + kc * 32);
            #pragma unroll
            for (int jt = 0; jt < 4; ++jt) {
                uint32_t b[4];
                ldm_x4_t(b, bb + bRowOff + kc * 16 * B_STRIDE + jt * 32);
                mma16816(acc[0][2 * jt],     a0, b);
                mma16816(acc[0][2 * jt + 1], a0, b + 2);
                mma16816(acc[1][2 * jt],     a1, b);
                mma16816(acc[1][2 * jt + 1], a1, b + 2);
            }
        }
        // k8 tail: A cols 96..111B (k rows 48..55 of B)
        uint32_t at[4];
        ldm_x4(at, ab + aTailOff);                 // m32 x k8
        #pragma unroll
        for (int half = 0; half < 2; ++half) {
            uint32_t b[4];
            ldm_x4_t(b, bb + bTailOff + half * 64);   // k8 x n32
            #pragma unroll
            for (int q = 0; q < 4; ++q) {
                mma1688(acc[0][half * 4 + q], at,     b[q]);
                mma1688(acc[1][half * 4 + q], at + 2, b[q]);
            }
        }
    };

    // ---- prologue: x(0), x(1), B(0) ----
    issue_x(0);
    issue_x(1);
    issue_b(0);
    CP_COMMIT();
    CP_WAIT0();
    __syncthreads();
    build_a(0);
    __syncthreads();

    // ---- main loop: one sync per stage; build(s+1) overlaps mma(s) ----
    #pragma unroll 1
    for (int s = 0; s < NSTAGE; ++s) {
        if (s + 1 < NSTAGE) issue_b(s + 1);
        if (s + 2 < NSTAGE) issue_x(s + 2);
        CP_COMMIT();
        if (s + 1 < NSTAGE) build_a(s + 1);
        mma_stage(s);
        CP_WAIT0();
        __syncthreads();
    }

    // ---- epilogue: direct global stores ----
    const int pbase = p0 + warpM * 32 + (lane >> 2);
    const int obase = warpN * 64 + (lane & 3) * 2;
    float* ob = out + (size_t)n * COUT * HWSZ;
    #pragma unroll
    for (int mt = 0; mt < 2; ++mt) {
        #pragma unroll
        for (int j = 0; j < 8; ++j) {
            const int o = obase + j * 8;
            const int p = pbase + mt * 16;
            ob[(size_t)o * HWSZ + p]           = acc[mt][j][0];
            ob[(size_t)(o + 1) * HWSZ + p]     = acc[mt][j][1];
            ob[(size_t)o * HWSZ + p + 8]       = acc[mt][j][2];
            ob[(size_t)(o + 1) * HWSZ + p + 8] = acc[mt][j][3];
        }
    }
}

extern "C" void kernel_launch(void* const* d_in, const int* in_sizes, int n_in,
                              void* d_out, int out_size)
{
    const float* x      = (const float*)d_in[0];
    const float* offset = (const float*)d_in[1];
    const float* weight = (const float*)d_in[2];
    float* out          = (float*)d_out;

    static int smem_set = 0;
    if (!smem_set) {
        cudaFuncSetAttribute(dcn_mma_kernel,
                             cudaFuncAttributeMaxDynamicSharedMemorySize, SMEM_DYN);
        smem_set = 1;
    }

    prep_weights<<<(NSTAGE * 56 * 64 + 255) / 256, 256>>>(weight);
    dim3 grid(HWSZ / PT, NB);                 // 8 x 16 = 128 blocks, one wave
    dcn_mma_kernel<<<grid, NT, SMEM_DYN>>>(x, offset, out);
}

// round 6
// speedup vs baseline: 1.1514x; 1.1514x over previous
#include <cuda_runtime.h>
#include <cuda_bf16.h>
#include <cstdint>

#define NB      16
#define CIN     256
#define COUT    256
#define HWSZ    1024
#define PT      128
#define NSTAGE  128          // 2 input channels per stage
#define NT      512          // 16 warps, 4(M) x 4(N)

// K order (56 cols): col = k*6 + term*2 + ch  (k=0..8, term 0:hi*hi 1:lo*hi 2:hi*lo, ch 0/1)
// cols 54,55 = zero pad.  A holds [h0,h1,l0,l1,h0,h1] per k; B holds [whi,whi,whi,whi,wlo,wlo].
#define A_STRIDE 112                 // 56 cols; ldmatrix conflict-free (28-word stride)
#define A_SZ     (128 * A_STRIDE)    // 14336
#define B_STRIDE 528                 // 256 cols + 8 pad
#define B_SZ     (56 * B_STRIDE)     // 29568
#define X_SZ     8192                // 2 channels x 1024 float
#define A_OFF    0
#define B_OFF    (2 * A_SZ)          // 28672
#define X_OFF    (B_OFF + 2 * B_SZ)  // 87808
#define SMEM_DYN (X_OFF + 3 * X_SZ)  // 112384

// packed weights: [stage][56 k][256 o] bf16, rows 512B
__device__ __align__(16) unsigned char g_wp[(size_t)NSTAGE * 56 * 512];

// ---------------- helpers ----------------
__device__ __forceinline__ uint32_t smem_u32(const void* p) {
    uint32_t a;
    asm("{ .reg .u64 t; cvta.to.shared.u64 t, %1; cvt.u32.u64 %0, t; }" : "=r"(a) : "l"(p));
    return a;
}
__device__ __forceinline__ void cp16(uint32_t d, const void* g) {
    asm volatile("cp.async.cg.shared.global [%0], [%1], 16;" :: "r"(d), "l"(g));
}
#define CP_COMMIT() asm volatile("cp.async.commit_group;" ::: "memory")
#define CP_WAIT0()  asm volatile("cp.async.wait_group 0;" ::: "memory")

__device__ __forceinline__ void ldm_x4(uint32_t r[4], uint32_t a) {
    asm volatile("ldmatrix.sync.aligned.m8n8.x4.shared.b16 {%0,%1,%2,%3}, [%4];"
                 : "=r"(r[0]), "=r"(r[1]), "=r"(r[2]), "=r"(r[3]) : "r"(a));
}
__device__ __forceinline__ void ldm_x4_t(uint32_t r[4], uint32_t a) {
    asm volatile("ldmatrix.sync.aligned.m8n8.x4.trans.shared.b16 {%0,%1,%2,%3}, [%4];"
                 : "=r"(r[0]), "=r"(r[1]), "=r"(r[2]), "=r"(r[3]) : "r"(a));
}
__device__ __forceinline__ void mma16816(float d[4], const uint32_t a[4], const uint32_t b[2]) {
    asm volatile("mma.sync.aligned.m16n8k16.row.col.f32.bf16.bf16.f32 "
                 "{%0,%1,%2,%3},{%4,%5,%6,%7},{%8,%9},{%0,%1,%2,%3};"
                 : "+f"(d[0]), "+f"(d[1]), "+f"(d[2]), "+f"(d[3])
                 : "r"(a[0]), "r"(a[1]), "r"(a[2]), "r"(a[3]), "r"(b[0]), "r"(b[1]));
}
__device__ __forceinline__ void mma1688(float d[4], const uint32_t a[2], uint32_t b) {
    asm volatile("mma.sync.aligned.m16n8k8.row.col.f32.bf16.bf16.f32 "
                 "{%0,%1,%2,%3},{%4,%5},{%6},{%0,%1,%2,%3};"
                 : "+f"(d[0]), "+f"(d[1]), "+f"(d[2]), "+f"(d[3])
                 : "r"(a[0]), "r"(a[1]), "r"(b));
}

// ---------------- weight prep: split hi/lo, k-major (new K order), 8B writes ----------------
__global__ void prep_weights(const float* __restrict__ weight) {
    const int j = blockIdx.x * blockDim.x + threadIdx.x;   // 128*56*64
    if (j >= NSTAGE * 56 * 64) return;
    const int o4 = j & 63;
    const int kcol = (j >> 6) % 56;
    const int s = j / (56 * 64);
    __nv_bfloat16 v[4];
    if (kcol >= 54) {
        v[0] = v[1] = v[2] = v[3] = __float2bfloat16(0.f);
    } else {
        const int k = kcol / 6, rem = kcol % 6, t = rem >> 1, ch = rem & 1;
        #pragma unroll
        for (int i = 0; i < 4; ++i) {
            const float w = weight[(size_t)(4 * o4 + i) * 2304 + (2 * s + ch) * 9 + k];
            const __nv_bfloat16 hi = __float2bfloat16(w);
            v[i] = (t == 2) ? __float2bfloat16(w - __bfloat162float(hi)) : hi;
        }
    }
    *(uint2*)(g_wp + ((size_t)s * 56 + kcol) * 512 + o4 * 8) = *(const uint2*)v;
}

// ---------------- main kernel ----------------
__global__ __launch_bounds__(NT)
void dcn_mma_kernel(const float* __restrict__ x,
                    const float* __restrict__ offset,
                    float* __restrict__ out)
{
    extern __shared__ char sm[];
    const uint32_t sb = smem_u32(sm);

    const int tid  = threadIdx.x;
    const int wid  = tid >> 5, lane = tid & 31;
    const int n    = blockIdx.y;
    const int p0   = blockIdx.x * PT;
    const int warpM = wid & 3;     // 4 M-tiles of 32
    const int warpN = wid >> 2;    // 4 N-tiles of 64

    // zero A pad cols (bytes 108..111) of both buffers
    if (tid < 256)
        *(uint32_t*)(sm + A_OFF + (tid >> 7) * A_SZ + (tid & 127) * A_STRIDE + 108) = 0;

    // ---- sampling tables -> registers (3 entries/thread) ----
    uint32_t tlo[3], thi[3];
    float4 twt[3];
    #pragma unroll
    for (int e = 0; e < 3; ++e) {
        const int j = tid + e * NT;
        if (j < 9 * PT) {
            const int k = j >> 7, p = j & 127;
            const int gp = p0 + p;
            const float2 d2 = *reinterpret_cast<const float2*>(
                offset + ((size_t)n * HWSZ + gp) * 18 + 2 * k);
            const float py = (float)(gp >> 5) + (float)(k / 3 - 1) + d2.x;
            const float px = (float)(gp & 31) + (float)(k % 3 - 1) + d2.y;
            const float y0 = floorf(py), x0 = floorf(px);
            const float ly = py - y0, lx = px - x0;
            const float hy = 1.f - ly, hx = 1.f - lx;
            const float vy0 = (y0 >= 0.f && y0 <= 31.f) ? 1.f : 0.f;
            const float vy1 = (y0 >= -1.f && y0 <= 30.f) ? 1.f : 0.f;
            const float vx0 = (x0 >= 0.f && x0 <= 31.f) ? 1.f : 0.f;
            const float vx1 = (x0 >= -1.f && x0 <= 30.f) ? 1.f : 0.f;
            const uint32_t iy0 = (uint32_t)(int)fminf(fmaxf(y0, 0.f), 31.f);
            const uint32_t iy1 = (uint32_t)(int)fminf(fmaxf(y0 + 1.f, 0.f), 31.f);
            const uint32_t ix0 = (uint32_t)(int)fminf(fmaxf(x0, 0.f), 31.f);
            const uint32_t ix1 = (uint32_t)(int)fminf(fmaxf(x0 + 1.f, 0.f), 31.f);
            tlo[e] = (iy0 * 32 + ix0) | ((iy0 * 32 + ix1) << 16);
            thi[e] = (iy1 * 32 + ix0) | ((iy1 * 32 + ix1) << 16);
            twt[e] = make_float4(hy * hx * vy0 * vx0, hy * lx * vy0 * vx1,
                                 ly * hx * vy1 * vx0, ly * lx * vy1 * vx1);
        } else {
            tlo[e] = thi[e] = 0;
            twt[e] = make_float4(0.f, 0.f, 0.f, 0.f);
        }
    }

    const float* xn = x + (size_t)n * CIN * HWSZ;

    // ---- async staging ----
    auto issue_b = [&](int st) {   // B(st) <- g_wp[st], 1792 x 16B
        const char* gsrc = (const char*)g_wp + (size_t)st * (56 * 512);
        const uint32_t bdst = sb + B_OFF + (st & 1) * B_SZ;
        #pragma unroll
        for (int q = 0; q < 4; ++q) {
            const int idx = tid + q * NT;
            if (q < 3 || idx < 1792) {
                const int row = idx >> 5, ch = idx & 31;
                cp16(bdst + row * B_STRIDE + ch * 16, gsrc + row * 512 + ch * 16);
            }
        }
    };
    auto issue_x = [&](int st) {
        cp16(sb + X_OFF + (st % 3) * X_SZ + tid * 16,
             (const char*)(xn + (size_t)(2 * st) * HWSZ) + tid * 16);
    };

    // ---- build deformed, bf16-split A tile (3x STS.32 per element) ----
    auto build_a = [&](int st) {
        const float* xp0 = (const float*)(sm + X_OFF + (st % 3) * X_SZ);
        const float* xp1 = xp0 + 1024;
        char* abuf = sm + A_OFF + (st & 1) * A_SZ;
        #pragma unroll
        for (int e = 0; e < 3; ++e) {
            const int j = tid + e * NT;
            if (e == 2 && j >= 9 * PT) break;
            const int k = j >> 7, p = j & 127;
            const int i00 = tlo[e] & 0xFFFF, i01 = tlo[e] >> 16;
            const int i10 = thi[e] & 0xFFFF, i11 = thi[e] >> 16;
            const float4 w = twt[e];
            const float v0 = w.x * xp0[i00] + w.y * xp0[i01] + w.z * xp0[i10] + w.w * xp0[i11];
            const float v1 = w.x * xp1[i00] + w.y * xp1[i01] + w.z * xp1[i10] + w.w * xp1[i11];
            const __nv_bfloat16 h0 = __float2bfloat16(v0);
            const __nv_bfloat16 l0 = __float2bfloat16(v0 - __bfloat162float(h0));
            const __nv_bfloat16 h1 = __float2bfloat16(v1);
            const __nv_bfloat16 l1 = __float2bfloat16(v1 - __bfloat162float(h1));
            const uint32_t hh = ((uint32_t)*(const unsigned short*)&h1 << 16)
                              |  (uint32_t)*(const unsigned short*)&h0;
            const uint32_t ll = ((uint32_t)*(const unsigned short*)&l1 << 16)
                              |  (uint32_t)*(const unsigned short*)&l0;
            char* dst = abuf + p * A_STRIDE + k * 12;
            *(uint32_t*)(dst)     = hh;   // term0: vhi ch0, ch1
            *(uint32_t*)(dst + 4) = ll;   // term1: vlo ch0, ch1
            *(uint32_t*)(dst + 8) = hh;   // term2: vhi ch0, ch1 (x wlo)
        }
    };

    // ---- accumulators ----
    float acc[2][8][4];
    #pragma unroll
    for (int i = 0; i < 2; ++i)
        #pragma unroll
        for (int j = 0; j < 8; ++j)
            #pragma unroll
            for (int q = 0; q < 4; ++q) acc[i][j][q] = 0.f;

    // ldmatrix address components (constant across stages)
    const uint32_t aRowOff  = (uint32_t)(warpM * 32 + (lane & 15)) * A_STRIDE
                            + (uint32_t)(lane >> 4) * 16;
    const uint32_t aTailOff = (uint32_t)(warpM * 32 + lane) * A_STRIDE + 96;
    const uint32_t bRowOff  = (uint32_t)(lane & 15) * B_STRIDE
                            + (uint32_t)(warpN * 128) + (uint32_t)(lane >> 4) * 16;
    const uint32_t bTailOff = (uint32_t)(48 + (lane & 7)) * B_STRIDE
                            + (uint32_t)(warpN * 128) + (uint32_t)((lane >> 3) & 3) * 16;

    auto mma_stage = [&](int st) {
        const uint32_t ab = sb + A_OFF + (st & 1) * A_SZ;
        const uint32_t bb = sb + B_OFF + (st & 1) * B_SZ;
        #pragma unroll
        for (int kc = 0; kc < 3; ++kc) {
            uint32_t a0[4], a1[4];
            ldm_x4(a0, ab + aRowOff + kc * 32);
            ldm_x4(a1, ab + aRowOff + 16 * A_STRIDE + kc * 32);
            #pragma unroll
            for (int jt = 0; jt < 4; ++jt) {
                uint32_t b[4];
                ldm_x4_t(b, bb + bRowOff + kc * 16 * B_STRIDE + jt * 32);
                mma16816(acc[0][2 * jt],     a0, b);
                mma16816(acc[0][2 * jt + 1], a0, b + 2);
                mma16816(acc[1][2 * jt],     a1, b);
                mma16816(acc[1][2 * jt + 1], a1, b + 2);
            }
        }
        // k8 tail: A cols 48..55 (bytes 96..111), B rows 48..55
        uint32_t at[4];
        ldm_x4(at, ab + aTailOff);
        #pragma unroll
        for (int half = 0; half < 2; ++half) {
            uint32_t b[4];
            ldm_x4_t(b, bb + bTailOff + half * 64);
            #pragma unroll
            for (int q = 0; q < 4; ++q) {
                mma1688(acc[0][half * 4 + q], at,     b[q]);
                mma1688(acc[1][half * 4 + q], at + 2, b[q]);
            }
        }
    };

    // ---- prologue: x(0), x(1), B(0) ----
    issue_x(0);
    issue_x(1);
    issue_b(0);
    CP_COMMIT();
    CP_WAIT0();
    __syncthreads();
    build_a(0);
    __syncthreads();

    // ---- main loop: warp-parity stagger breaks build/MMA phase alignment ----
    #pragma unroll 1
    for (int s = 0; s < NSTAGE; ++s) {
        const bool more = (s + 1 < NSTAGE);
        if (more) issue_b(s + 1);
        if (s + 2 < NSTAGE) issue_x(s + 2);
        CP_COMMIT();
        if (wid & 1) {
            if (more) build_a(s + 1);
            mma_stage(s);
        } else {
            mma_stage(s);
            if (more) build_a(s + 1);
        }
        CP_WAIT0();
        __syncthreads();
    }

    // ---- epilogue: direct global stores ----
    const int pbase = p0 + warpM * 32 + (lane >> 2);
    const int obase = warpN * 64 + (lane & 3) * 2;
    float* ob = out + (size_t)n * COUT * HWSZ;
    #pragma unroll
    for (int mt = 0; mt < 2; ++mt) {
        #pragma unroll
        for (int j = 0; j < 8; ++j) {
            const int o = obase + j * 8;
            const int p = pbase + mt * 16;
            ob[(size_t)o * HWSZ + p]           = acc[mt][j][0];
            ob[(size_t)(o + 1) * HWSZ + p]     = acc[mt][j][1];
            ob[(size_t)o * HWSZ + p + 8]       = acc[mt][j][2];
            ob[(size_t)(o + 1) * HWSZ + p + 8] = acc[mt][j][3];
        }
    }
}

extern "C" void kernel_launch(void* const* d_in, const int* in_sizes, int n_in,
                              void* d_out, int out_size)
{
    const float* x      = (const float*)d_in[0];
    const float* offset = (const float*)d_in[1];
    const float* weight = (const float*)d_in[2];
    float* out          = (float*)d_out;

    static int smem_set = 0;
    if (!smem_set) {
        cudaFuncSetAttribute(dcn_mma_kernel,
                             cudaFuncAttributeMaxDynamicSharedMemorySize, SMEM_DYN);
        smem_set = 1;
    }

    prep_weights<<<(NSTAGE * 56 * 64 + 255) / 256, 256>>>(weight);
    dim3 grid(HWSZ / PT, NB);                 // 8 x 16 = 128 blocks, one wave
    dcn_mma_kernel<<<grid, NT, SMEM_DYN>>>(x, offset, out);
}

// round 7
// speedup vs baseline: 1.2673x; 1.1007x over previous
#include <cuda_runtime.h>
#include <cuda_bf16.h>
#include <cstdint>

#define NB      16
#define CIN     256
#define COUT    256
#define HWSZ    1024
#define PT      128
#define NSTAGE  128          // 2 input channels per stage
#define NT      256          // 8 warps, 2(M) x 4(N), 64x64 warp tiles

// K order (56 cols): col = k*6 + term*2 + ch  (term 0:hi*hi 1:lo*hi 2:hi*lo)
#define A_STRIDE 112
#define A_SZ     (128 * A_STRIDE)    // 14336
#define B_STRIDE 528
#define B_SZ     (56 * B_STRIDE)     // 29568
#define X_SZ     8192
#define A_OFF    0
#define B_OFF    (2 * A_SZ)          // 28672
#define X_OFF    (B_OFF + 2 * B_SZ)  // 87808
#define SMEM_DYN (X_OFF + 3 * X_SZ)  // 112384

__device__ __align__(16) unsigned char g_wp[(size_t)NSTAGE * 56 * 512];

// ---------------- helpers ----------------
__device__ __forceinline__ uint32_t smem_u32(const void* p) {
    uint32_t a;
    asm("{ .reg .u64 t; cvta.to.shared.u64 t, %1; cvt.u32.u64 %0, t; }" : "=r"(a) : "l"(p));
    return a;
}
__device__ __forceinline__ void cp16(uint32_t d, const void* g) {
    asm volatile("cp.async.cg.shared.global [%0], [%1], 16;" :: "r"(d), "l"(g));
}
#define CP_COMMIT() asm volatile("cp.async.commit_group;" ::: "memory")
#define CP_WAIT0()  asm volatile("cp.async.wait_group 0;" ::: "memory")

__device__ __forceinline__ void ldm_x4(uint32_t r[4], uint32_t a) {
    asm volatile("ldmatrix.sync.aligned.m8n8.x4.shared.b16 {%0,%1,%2,%3}, [%4];"
                 : "=r"(r[0]), "=r"(r[1]), "=r"(r[2]), "=r"(r[3]) : "r"(a));
}
__device__ __forceinline__ void ldm_x4_t(uint32_t r[4], uint32_t a) {
    asm volatile("ldmatrix.sync.aligned.m8n8.x4.trans.shared.b16 {%0,%1,%2,%3}, [%4];"
                 : "=r"(r[0]), "=r"(r[1]), "=r"(r[2]), "=r"(r[3]) : "r"(a));
}
__device__ __forceinline__ void mma16816(float d[4], const uint32_t a[4], const uint32_t b[2]) {
    asm volatile("mma.sync.aligned.m16n8k16.row.col.f32.bf16.bf16.f32 "
                 "{%0,%1,%2,%3},{%4,%5,%6,%7},{%8,%9},{%0,%1,%2,%3};"
                 : "+f"(d[0]), "+f"(d[1]), "+f"(d[2]), "+f"(d[3])
                 : "r"(a[0]), "r"(a[1]), "r"(a[2]), "r"(a[3]), "r"(b[0]), "r"(b[1]));
}
__device__ __forceinline__ void mma1688(float d[4], const uint32_t a[2], uint32_t b) {
    asm volatile("mma.sync.aligned.m16n8k8.row.col.f32.bf16.bf16.f32 "
                 "{%0,%1,%2,%3},{%4,%5},{%6},{%0,%1,%2,%3};"
                 : "+f"(d[0]), "+f"(d[1]), "+f"(d[2]), "+f"(d[3])
                 : "r"(a[0]), "r"(a[1]), "r"(b));
}

// ---------------- weight prep (unchanged layout) ----------------
__global__ void prep_weights(const float* __restrict__ weight) {
    const int j = blockIdx.x * blockDim.x + threadIdx.x;
    if (j >= NSTAGE * 56 * 64) return;
    const int o4 = j & 63;
    const int kcol = (j >> 6) % 56;
    const int s = j / (56 * 64);
    __nv_bfloat16 v[4];
    if (kcol >= 54) {
        v[0] = v[1] = v[2] = v[3] = __float2bfloat16(0.f);
    } else {
        const int k = kcol / 6, rem = kcol % 6, t = rem >> 1, ch = rem & 1;
        #pragma unroll
        for (int i = 0; i < 4; ++i) {
            const float w = weight[(size_t)(4 * o4 + i) * 2304 + (2 * s + ch) * 9 + k];
            const __nv_bfloat16 hi = __float2bfloat16(w);
            v[i] = (t == 2) ? __float2bfloat16(w - __bfloat162float(hi)) : hi;
        }
    }
    *(uint2*)(g_wp + ((size_t)s * 56 + kcol) * 512 + o4 * 8) = *(const uint2*)v;
}

// ---------------- main kernel ----------------
__global__ __launch_bounds__(NT, 1)
void dcn_mma_kernel(const float* __restrict__ x,
                    const float* __restrict__ offset,
                    float* __restrict__ out)
{
    extern __shared__ char sm[];
    const uint32_t sb = smem_u32(sm);

    const int tid  = threadIdx.x;
    const int wid  = tid >> 5, lane = tid & 31;
    const int n    = blockIdx.y;
    const int p0   = blockIdx.x * PT;
    const int warpM = wid & 1;            // 2 M-tiles of 64
    const int warpN = (wid >> 1) & 3;     // 4 N-tiles of 64
    const int pbit  = (wid >> 2) & 1;     // co-resident SMSP warps differ

    // zero A pad cols (bytes 108..111) of both buffers (256 rows total)
    *(uint32_t*)(sm + A_OFF + (tid >> 7) * A_SZ + (tid & 127) * A_STRIDE + 108) = 0;

    // ---- sampling tables -> registers (5 entries/thread) ----
    uint32_t tlo[5], thi[5];
    float4 twt[5];
    #pragma unroll
    for (int e = 0; e < 5; ++e) {
        const int j = tid + e * NT;
        if (j < 9 * PT) {
            const int k = j >> 7, p = j & 127;
            const int gp = p0 + p;
            const float2 d2 = *reinterpret_cast<const float2*>(
                offset + ((size_t)n * HWSZ + gp) * 18 + 2 * k);
            const float py = (float)(gp >> 5) + (float)(k / 3 - 1) + d2.x;
            const float px = (float)(gp & 31) + (float)(k % 3 - 1) + d2.y;
            const float y0 = floorf(py), x0 = floorf(px);
            const float ly = py - y0, lx = px - x0;
            const float hy = 1.f - ly, hx = 1.f - lx;
            const float vy0 = (y0 >= 0.f && y0 <= 31.f) ? 1.f : 0.f;
            const float vy1 = (y0 >= -1.f && y0 <= 30.f) ? 1.f : 0.f;
            const float vx0 = (x0 >= 0.f && x0 <= 31.f) ? 1.f : 0.f;
            const float vx1 = (x0 >= -1.f && x0 <= 30.f) ? 1.f : 0.f;
            const uint32_t iy0 = (uint32_t)(int)fminf(fmaxf(y0, 0.f), 31.f);
            const uint32_t iy1 = (uint32_t)(int)fminf(fmaxf(y0 + 1.f, 0.f), 31.f);
            const uint32_t ix0 = (uint32_t)(int)fminf(fmaxf(x0, 0.f), 31.f);
            const uint32_t ix1 = (uint32_t)(int)fminf(fmaxf(x0 + 1.f, 0.f), 31.f);
            tlo[e] = (iy0 * 32 + ix0) | ((iy0 * 32 + ix1) << 16);
            thi[e] = (iy1 * 32 + ix0) | ((iy1 * 32 + ix1) << 16);
            twt[e] = make_float4(hy * hx * vy0 * vx0, hy * lx * vy0 * vx1,
                                 ly * hx * vy1 * vx0, ly * lx * vy1 * vx1);
        } else {
            tlo[e] = thi[e] = 0;
            twt[e] = make_float4(0.f, 0.f, 0.f, 0.f);
        }
    }

    const float* xn = x + (size_t)n * CIN * HWSZ;

    // ---- async staging ----
    auto issue_b = [&](int st) {   // 1792 x 16B = 7/thread
        const char* gsrc = (const char*)g_wp + (size_t)st * (56 * 512);
        const uint32_t bdst = sb + B_OFF + (st & 1) * B_SZ;
        #pragma unroll
        for (int q = 0; q < 7; ++q) {
            const int idx = tid + q * NT;
            const int row = idx >> 5, ch = idx & 31;
            cp16(bdst + row * B_STRIDE + ch * 16, gsrc + row * 512 + ch * 16);
        }
    };
    auto issue_x = [&](int st) {   // 8KB = 2/thread
        const uint32_t xd = sb + X_OFF + (st % 3) * X_SZ;
        const char* gs = (const char*)(xn + (size_t)(2 * st) * HWSZ);
        cp16(xd + tid * 16, gs + tid * 16);
        cp16(xd + (tid + NT) * 16, gs + (tid + NT) * 16);
    };

    // ---- build deformed, bf16-split A tile ----
    auto build_a = [&](int st) {
        const float* xp0 = (const float*)(sm + X_OFF + (st % 3) * X_SZ);
        const float* xp1 = xp0 + 1024;
        char* abuf = sm + A_OFF + (st & 1) * A_SZ;
        #pragma unroll
        for (int e = 0; e < 5; ++e) {
            const int j = tid + e * NT;
            if (e == 4 && j >= 9 * PT) break;
            const int k = j >> 7, p = j & 127;
            const int i00 = tlo[e] & 0xFFFF, i01 = tlo[e] >> 16;
            const int i10 = thi[e] & 0xFFFF, i11 = thi[e] >> 16;
            const float4 w = twt[e];
            const float v0 = w.x * xp0[i00] + w.y * xp0[i01] + w.z * xp0[i10] + w.w * xp0[i11];
            const float v1 = w.x * xp1[i00] + w.y * xp1[i01] + w.z * xp1[i10] + w.w * xp1[i11];
            const __nv_bfloat16 h0 = __float2bfloat16(v0);
            const __nv_bfloat16 l0 = __float2bfloat16(v0 - __bfloat162float(h0));
            const __nv_bfloat16 h1 = __float2bfloat16(v1);
            const __nv_bfloat16 l1 = __float2bfloat16(v1 - __bfloat162float(h1));
            const uint32_t hh = ((uint32_t)*(const unsigned short*)&h1 << 16)
                              |  (uint32_t)*(const unsigned short*)&h0;
            const uint32_t ll = ((uint32_t)*(const unsigned short*)&l1 << 16)
                              |  (uint32_t)*(const unsigned short*)&l0;
            char* dst = abuf + p * A_STRIDE + k * 12;
            *(uint32_t*)(dst)     = hh;
            *(uint32_t*)(dst + 4) = ll;
            *(uint32_t*)(dst + 8) = hh;
        }
    };

    // ---- accumulators: 4 m16 x 8 n8 ----
    float acc[4][8][4];
    #pragma unroll
    for (int i = 0; i < 4; ++i)
        #pragma unroll
        for (int j = 0; j < 8; ++j)
            #pragma unroll
            for (int q = 0; q < 4; ++q) acc[i][j][q] = 0.f;

    const uint32_t aRowOff  = (uint32_t)(warpM * 64 + (lane & 15)) * A_STRIDE
                            + (uint32_t)(lane >> 4) * 16;
    const uint32_t aTailOff = (uint32_t)(warpM * 64 + lane) * A_STRIDE + 96;
    const uint32_t bRowOff  = (uint32_t)(lane & 15) * B_STRIDE
                            + (uint32_t)(warpN * 128) + (uint32_t)(lane >> 4) * 16;
    const uint32_t bTailOff = (uint32_t)(48 + (lane & 7)) * B_STRIDE
                            + (uint32_t)(warpN * 128) + (uint32_t)((lane >> 3) & 3) * 16;

    auto mma_stage = [&](int st) {
        const uint32_t ab = sb + A_OFF + (st & 1) * A_SZ;
        const uint32_t bb = sb + B_OFF + (st & 1) * B_SZ;
        #pragma unroll
        for (int kc = 0; kc < 3; ++kc) {
            uint32_t a[4][4];
            #pragma unroll
            for (int mi = 0; mi < 4; ++mi)
                ldm_x4(a[mi], ab + aRowOff + mi * 16 * A_STRIDE + kc * 32);
            #pragma unroll
            for (int jt = 0; jt < 4; ++jt) {
                uint32_t b[4];
                ldm_x4_t(b, bb + bRowOff + kc * 16 * B_STRIDE + jt * 32);
                #pragma unroll
                for (int mi = 0; mi < 4; ++mi) {
                    mma16816(acc[mi][2 * jt],     a[mi], b);
                    mma16816(acc[mi][2 * jt + 1], a[mi], b + 2);
                }
            }
        }
        // k8 tail: A cols 48..55, B rows 48..55
        uint32_t at[8];
        ldm_x4(at,     ab + aTailOff);
        ldm_x4(at + 4, ab + aTailOff + 32 * A_STRIDE);
        #pragma unroll
        for (int half = 0; half < 2; ++half) {
            uint32_t b[4];
            ldm_x4_t(b, bb + bTailOff + half * 64);
            #pragma unroll
            for (int mi = 0; mi < 4; ++mi)
                #pragma unroll
                for (int q = 0; q < 4; ++q)
                    mma1688(acc[mi][half * 4 + q], at + mi * 2, b[q]);
        }
    };

    // ---- prologue ----
    issue_x(0);
    issue_x(1);
    issue_b(0);
    CP_COMMIT();
    CP_WAIT0();
    __syncthreads();
    build_a(0);
    __syncthreads();

    // ---- main loop: SMSP-correct stagger ----
    #pragma unroll 1
    for (int s = 0; s < NSTAGE; ++s) {
        const bool more = (s + 1 < NSTAGE);
        if (more) issue_b(s + 1);
        if (s + 2 < NSTAGE) issue_x(s + 2);
        CP_COMMIT();
        if (pbit) {
            if (more) build_a(s + 1);
            mma_stage(s);
        } else {
            mma_stage(s);
            if (more) build_a(s + 1);
        }
        CP_WAIT0();
        __syncthreads();
    }

    // ---- epilogue ----
    const int pbase = p0 + warpM * 64 + (lane >> 2);
    const int obase = warpN * 64 + (lane & 3) * 2;
    float* ob = out + (size_t)n * COUT * HWSZ;
    #pragma unroll
    for (int mt = 0; mt < 4; ++mt) {
        #pragma unroll
        for (int j = 0; j < 8; ++j) {
            const int o = obase + j * 8;
            const int p = pbase + mt * 16;
            ob[(size_t)o * HWSZ + p]           = acc[mt][j][0];
            ob[(size_t)(o + 1) * HWSZ + p]     = acc[mt][j][1];
            ob[(size_t)o * HWSZ + p + 8]       = acc[mt][j][2];
            ob[(size_t)(o + 1) * HWSZ + p + 8] = acc[mt][j][3];
        }
    }
}

extern "C" void kernel_launch(void* const* d_in, const int* in_sizes, int n_in,
                              void* d_out, int out_size)
{
    const float* x      = (const float*)d_in[0];
    const float* offset = (const float*)d_in[1];
    const float* weight = (const float*)d_in[2];
    float* out          = (float*)d_out;

    static int smem_set = 0;
    if (!smem_set) {
        cudaFuncSetAttribute(dcn_mma_kernel,
                             cudaFuncAttributeMaxDynamicSharedMemorySize, SMEM_DYN);
        smem_set = 1;
    }

    prep_weights<<<(NSTAGE * 56 * 64 + 255) / 256, 256>>>(weight);
    dim3 grid(HWSZ / PT, NB);                 // 8 x 16 = 128 blocks, one wave
    dcn_mma_kernel<<<grid, NT, SMEM_DYN>>>(x, offset, out);
}